// round 13
// baseline (speedup 1.0000x reference)
#include <cuda_runtime.h>
#include <cstdint>
#include <math.h>

// Problem constants
#define NB        4
#define SEQN      2048
#define DMODEL    256
#define HEADS     4
#define HD        64
#define ROWS_HALF 8192      // NB * SEQN
#define ROWS_TOT  16384     // 2 * NB * SEQN

// ---------------- scratch (no allocs allowed) ----------------
__device__ float g_qk [2 * NB * HEADS * SEQN * HD];  // [t][b][h][n][hd]
__device__ float g_qkT[2 * NB * HEADS * HD * SEQN];  // [t][b][h][hd][n]  (K^T for S-mma)
__device__ float g_v  [2 * NB * HEADS * SEQN * HD];  // [t][b][h][n][hd]
__device__ float g_m  [ROWS_TOT * DMODEL];           // attention out, head-merged
__device__ float g_mo [ROWS_TOT * DMODEL];           // after Wout
__device__ float g_y  [ROWS_TOT * 512];              // after W0 / LN / gelu

// ================= tf32 mma.sync helpers (sm_80+ PTX, ok for compute_103) =====
__device__ __forceinline__ uint32_t f2tf32(float x) {
    uint32_t r;
    asm("cvt.rna.tf32.f32 %0, %1;" : "=r"(r) : "f"(x));
    return r;
}
// D(16x8) += A(16x8,row) * B(8x8,col).
// acc: d0=(g,2t) d1=(g,2t+1) d2=(g+8,2t) d3=(g+8,2t+1)
__device__ __forceinline__ void mma_tf32(float acc[4], const uint32_t a[4],
                                         uint32_t b0, uint32_t b1) {
    asm volatile(
        "mma.sync.aligned.m16n8k8.row.col.f32.tf32.tf32.f32 "
        "{%0,%1,%2,%3}, {%4,%5,%6,%7}, {%8,%9}, {%0,%1,%2,%3};\n"
        : "+f"(acc[0]), "+f"(acc[1]), "+f"(acc[2]), "+f"(acc[3])
        : "r"(a[0]), "r"(a[1]), "r"(a[2]), "r"(a[3]), "r"(b0), "r"(b1));
}
__device__ __forceinline__ uint32_t swz(uint32_t gidx) {
    return gidx ^ ((gidx >> 2) & 7u);
}

// ================= fragment-layout tf32 GEMM mainloop (validated R11) =========
__device__ __forceinline__ void gemm_tf32(
    uint32_t As[2][512][4], uint32_t Bs[2][512][4],
    const float* A0, int lda0, const float* A1, int lda1, int splitc,
    const float* Bw, int ldb, int n0, int NC, float acc[2][8][4])
{
    int tid = threadIdx.x;
    int lane = tid & 31;
    int wid = tid >> 5, wm = wid & 3, wn = wid >> 4 >> 1;
    wn = wid >> 2;  // keep exact R11 semantics

    int ar = tid >> 1, acl = tid & 1;
    int a_mtile = ar >> 4, a_mr = ar & 15, a_g = a_mr & 7, a_hi = a_mr >> 3;
    uint32_t a_base = (uint32_t)((a_mtile * 2 + acl) * 32 + a_g * 4);
    int br = tid & 15, nb = tid >> 4;
    int b_ks = br >> 3, b_kk = br & 7, b_tig = b_kk & 3, b_half = b_kk >> 2;
    int b_jw = b_ks * 2 + b_half;

    float4 ra0, ra1, rb0, rb1;

    {
        const float* Ab = (0 < splitc) ? A0 : A1;
        int lda = (0 < splitc) ? lda0 : lda1;
        const float* pa = Ab + (size_t)ar * lda + acl * 8;
        ra0 = *(const float4*)pa;
        ra1 = *(const float4*)(pa + 4);
        const float* pb = Bw + (size_t)br * ldb + n0 + nb * 8;
        rb0 = *(const float4*)pb;
        rb1 = *(const float4*)(pb + 4);
        float av[8] = {ra0.x, ra0.y, ra0.z, ra0.w, ra1.x, ra1.y, ra1.z, ra1.w};
        float bv[8] = {rb0.x, rb0.y, rb0.z, rb0.w, rb1.x, rb1.y, rb1.z, rb1.w};
#pragma unroll
        for (int i = 0; i < 8; ++i) {
            int tig = i & 3, half = i >> 2;
            As[0][swz(a_base + tig)][half * 2 + a_hi] = f2tf32(av[i]);
            Bs[0][swz((uint32_t)(nb * 32 + i * 4 + b_tig))][b_jw] = f2tf32(bv[i]);
        }
    }
    __syncthreads();

    for (int c = 0; c < NC; ++c) {
        int cur = c & 1;
        bool more = (c + 1 < NC);
        if (more) {
            int cn = c + 1;
            const float* Ab; int lda;
            if (cn < splitc) { Ab = A0 + (size_t)cn * 16; lda = lda0; }
            else             { Ab = A1 + (size_t)(cn - splitc) * 16; lda = lda1; }
            const float* pa = Ab + (size_t)ar * lda + acl * 8;
            ra0 = *(const float4*)pa;
            ra1 = *(const float4*)(pa + 4);
            const float* pb = Bw + (size_t)(cn * 16 + br) * ldb + n0 + nb * 8;
            rb0 = *(const float4*)pb;
            rb1 = *(const float4*)(pb + 4);
        }
        uint32_t af[2][2][4];
#pragma unroll
        for (int mt = 0; mt < 2; ++mt) {
            uint32_t gbase = (uint32_t)(((wm * 2 + mt) * 2) * 32 + lane);
            uint4 f0 = *(const uint4*)As[cur][swz(gbase)];
            uint4 f1 = *(const uint4*)As[cur][swz(gbase + 32)];
            af[mt][0][0] = f0.x; af[mt][0][1] = f0.y; af[mt][0][2] = f0.z; af[mt][0][3] = f0.w;
            af[mt][1][0] = f1.x; af[mt][1][1] = f1.y; af[mt][1][2] = f1.z; af[mt][1][3] = f1.w;
        }
#pragma unroll
        for (int nt = 0; nt < 8; ++nt) {
            uint4 fb = *(const uint4*)Bs[cur][swz((uint32_t)((wn * 8 + nt) * 32 + lane))];
#pragma unroll
            for (int mt = 0; mt < 2; ++mt) {
                mma_tf32(acc[mt][nt], af[mt][0], fb.x, fb.y);
                mma_tf32(acc[mt][nt], af[mt][1], fb.z, fb.w);
            }
        }
        if (more) {
            int nx = cur ^ 1;
            float av[8] = {ra0.x, ra0.y, ra0.z, ra0.w, ra1.x, ra1.y, ra1.z, ra1.w};
            float bv[8] = {rb0.x, rb0.y, rb0.z, rb0.w, rb1.x, rb1.y, rb1.z, rb1.w};
#pragma unroll
            for (int i = 0; i < 8; ++i) {
                int tig = i & 3, half = i >> 2;
                As[nx][swz(a_base + tig)][half * 2 + a_hi] = f2tf32(av[i]);
                Bs[nx][swz((uint32_t)(nb * 32 + i * 4 + b_tig))][b_jw] = f2tf32(bv[i]);
            }
        }
        __syncthreads();
    }
}

#define MMA_EPI_IDS                                       \
    int tid = threadIdx.x;                                \
    int lane = tid & 31, g = lane >> 2, tig = lane & 3;   \
    int wid = tid >> 5, wm = wid & 3, wn = wid >> 2;      \
    (void)lane;

// ---------------- kernel 1: qk / v projection (+ K^T write) ----------------
__global__ __launch_bounds__(256) void k_proj_mma(
    const float* __restrict__ x0, const float* __restrict__ x1,
    const float* __restrict__ Wqk, const float* __restrict__ bqk,
    const float* __restrict__ Wv,  const float* __restrict__ bv)
{
    __shared__ uint32_t As[2][512][4];
    __shared__ uint32_t Bs[2][512][4];
    int m0  = blockIdx.y * 128;
    int n0g = blockIdx.x * 128;           // 0..511
    bool isv = (n0g >= 256);
    const float* Bw   = isv ? Wv : Wqk;
    const float* bias = isv ? bv : bqk;
    int n0 = n0g & 255;
    const float* A0 = (m0 < ROWS_HALF) ? (x0 + (size_t)m0 * DMODEL)
                                       : (x1 + (size_t)(m0 - ROWS_HALF) * DMODEL);
    float acc[2][8][4] = {};
    gemm_tf32(As, Bs, A0, DMODEL, A0, DMODEL, 1 << 20, Bw, DMODEL, n0, 16, acc);

    MMA_EPI_IDS;
    int t = (m0 >= ROWS_HALF);
    int base = m0 - t * ROWS_HALF;
    int bb = base >> 11;
    float* dst = isv ? g_v : g_qk;
    size_t hb = (((size_t)t * NB + bb) * HEADS) * (size_t)SEQN * HD;
#pragma unroll
    for (int mt = 0; mt < 2; ++mt) {
        int r   = m0 + wm * 32 + mt * 16 + g;
        int nn0 = (r - t * ROWS_HALF) & 2047;
#pragma unroll
        for (int nt = 0; nt < 8; ++nt) {
            int c = n0 + wn * 64 + nt * 8 + 2 * tig;
            int h = c >> 6, hd = c & 63;
            float b0v = bias[c], b1v = bias[c + 1];
            float va = acc[mt][nt][0] + b0v, vb = acc[mt][nt][1] + b1v;
            float vc = acc[mt][nt][2] + b0v, vd = acc[mt][nt][3] + b1v;
            size_t d0 = hb + ((size_t)h * SEQN + nn0) * HD + hd;
            size_t d1 = hb + ((size_t)h * SEQN + nn0 + 8) * HD + hd;
            *(float2*)&dst[d0] = make_float2(va, vb);
            *(float2*)&dst[d1] = make_float2(vc, vd);
            if (!isv) {
                size_t tb = ((((size_t)t * NB + bb) * HEADS + h) * HD + hd) * (size_t)SEQN;
                g_qkT[tb + nn0]            = va;
                g_qkT[tb + SEQN + nn0]     = vb;
                g_qkT[tb + nn0 + 8]        = vc;
                g_qkT[tb + SEQN + nn0 + 8] = vd;
            }
        }
    }
}

// ---------------- kernel 3: mo = m @ Wout + bout ----------------
__global__ __launch_bounds__(256) void k_outproj_mma(
    const float* __restrict__ Wout, const float* __restrict__ bout)
{
    __shared__ uint32_t As[2][512][4];
    __shared__ uint32_t Bs[2][512][4];
    int m0 = blockIdx.y * 128;
    int n0 = blockIdx.x * 128;
    const float* A0 = g_m + (size_t)m0 * DMODEL;
    float acc[2][8][4] = {};
    gemm_tf32(As, Bs, A0, DMODEL, A0, DMODEL, 1 << 20, Wout, DMODEL, n0, 16, acc);

    MMA_EPI_IDS;
#pragma unroll
    for (int mt = 0; mt < 2; ++mt) {
        int r = m0 + wm * 32 + mt * 16 + g;
#pragma unroll
        for (int nt = 0; nt < 8; ++nt) {
            int c = n0 + wn * 64 + nt * 8 + 2 * tig;
            float b0v = bout[c], b1v = bout[c + 1];
            *(float2*)&g_mo[(size_t)r * DMODEL + c] =
                make_float2(acc[mt][nt][0] + b0v, acc[mt][nt][1] + b1v);
            *(float2*)&g_mo[(size_t)(r + 8) * DMODEL + c] =
                make_float2(acc[mt][nt][2] + b0v, acc[mt][nt][3] + b1v);
        }
    }
}

// ---------------- kernel 4: y = [x | mo] @ W0 + b0 ----------------
__global__ __launch_bounds__(256) void k_ffn0_mma(
    const float* __restrict__ x0, const float* __restrict__ x1,
    const float* __restrict__ W0, const float* __restrict__ b0)
{
    __shared__ uint32_t As[2][512][4];
    __shared__ uint32_t Bs[2][512][4];
    int m0 = blockIdx.y * 128;
    int n0 = blockIdx.x * 128;   // 0..511
    const float* ax = (m0 < ROWS_HALF) ? (x0 + (size_t)m0 * DMODEL)
                                       : (x1 + (size_t)(m0 - ROWS_HALF) * DMODEL);
    const float* am = g_mo + (size_t)m0 * DMODEL;
    float acc[2][8][4] = {};
    gemm_tf32(As, Bs, ax, DMODEL, am, DMODEL, 16, W0, 512, n0, 32, acc);

    MMA_EPI_IDS;
#pragma unroll
    for (int mt = 0; mt < 2; ++mt) {
        int r = m0 + wm * 32 + mt * 16 + g;
#pragma unroll
        for (int nt = 0; nt < 8; ++nt) {
            int c = n0 + wn * 64 + nt * 8 + 2 * tig;
            float b0v = b0[c], b1v = b0[c + 1];
            *(float2*)&g_y[(size_t)r * 512 + c] =
                make_float2(acc[mt][nt][0] + b0v, acc[mt][nt][1] + b1v);
            *(float2*)&g_y[(size_t)(r + 8) * 512 + c] =
                make_float2(acc[mt][nt][2] + b0v, acc[mt][nt][3] + b1v);
        }
    }
}

// ---------------- kernel 6: out = x + y @ W3 + b3 ----------------
__global__ __launch_bounds__(256) void k_ffn3_mma(
    const float* __restrict__ x0, const float* __restrict__ x1,
    const float* __restrict__ W3, const float* __restrict__ b3,
    float* __restrict__ out)
{
    __shared__ uint32_t As[2][512][4];
    __shared__ uint32_t Bs[2][512][4];
    int m0 = blockIdx.y * 128;
    int n0 = blockIdx.x * 128;   // 0..255
    const float* A0 = g_y + (size_t)m0 * 512;
    float acc[2][8][4] = {};
    gemm_tf32(As, Bs, A0, 512, A0, 512, 1 << 20, W3, DMODEL, n0, 32, acc);

    MMA_EPI_IDS;
    const float* xb = (m0 < ROWS_HALF) ? (x0 + (size_t)m0 * DMODEL)
                                       : (x1 + (size_t)(m0 - ROWS_HALF) * DMODEL);
#pragma unroll
    for (int mt = 0; mt < 2; ++mt) {
        int r  = m0 + wm * 32 + mt * 16 + g;
        int rl = wm * 32 + mt * 16 + g;
#pragma unroll
        for (int nt = 0; nt < 8; ++nt) {
            int c = n0 + wn * 64 + nt * 8 + 2 * tig;
            float b0v = b3[c], b1v = b3[c + 1];
            float2 xv0 = *(const float2*)(xb + (size_t)rl * DMODEL + c);
            float2 xv1 = *(const float2*)(xb + (size_t)(rl + 8) * DMODEL + c);
            *(float2*)&out[(size_t)r * DMODEL + c] =
                make_float2(acc[mt][nt][0] + b0v + xv0.x, acc[mt][nt][1] + b1v + xv0.y);
            *(float2*)&out[(size_t)(r + 8) * DMODEL + c] =
                make_float2(acc[mt][nt][2] + b0v + xv1.x, acc[mt][nt][3] + b1v + xv1.y);
        }
    }
}

// ---------------- kernel 2: tf32 mma flash attention ----------------
// Tile: 128 q x 64 kv per iteration, HD=64. 8 warps: wm 0..3 (M), wn 0..1 (N).
// S-acc[2][4][4]: warp tile 32x32 over S(128x64); O-acc likewise over O(128x64).
// Smem (dynamic, words): Qf[4][512][4] @0, Kf[4][256][4] @8192, Vf[4][256][4]
// @12288, Pf[4][512][4] @16384, smax[2][128] @24576, ssum[2][128] @24832.
#define ATTN_SMEM_WORDS 25088
#define ATTN_SMEM_BYTES (ATTN_SMEM_WORDS * 4)

__global__ __launch_bounds__(256) void k_attn_mma() {
    extern __shared__ uint32_t sm[];
    uint32_t (*Qf)[512][4] = (uint32_t(*)[512][4])(sm);
    uint32_t (*Kf)[256][4] = (uint32_t(*)[256][4])(sm + 8192);
    uint32_t (*Vf)[256][4] = (uint32_t(*)[256][4])(sm + 12288);
    uint32_t (*Pf)[512][4] = (uint32_t(*)[512][4])(sm + 16384);
    float* smax = (float*)(sm + 24576);   // [2][128]
    float* ssum = (float*)(sm + 24832);   // [2][128]

    int qt = blockIdx.x, bh = blockIdx.y, dir = blockIdx.z;
    int b = bh >> 2, h = bh & 3, kvd = 1 - dir;

    const float* Qb = g_qk  + (((size_t)dir * NB + b) * HEADS + h) * (size_t)SEQN * HD
                            + (size_t)qt * 128 * HD;
    const float* KT = g_qkT + (((size_t)kvd * NB + b) * HEADS + h) * (size_t)HD * SEQN;
    const float* Vb = g_v   + (((size_t)kvd * NB + b) * HEADS + h) * (size_t)SEQN * HD;

    int tid = threadIdx.x, lane = tid & 31, g = lane >> 2, tig = tid & 3;
    int wid = tid >> 5, wm = wid & 3, wn = wid >> 2;

    // ---- Q producer: A-frag, scale folded ----
    {
        int ar = tid >> 1, acl = tid & 1;
        int amt = ar >> 4, amr = ar & 15, ag = amr & 7, ahi = amr >> 3;
        uint32_t abase = (uint32_t)((amt * 2 + acl) * 32 + ag * 4);
#pragma unroll
        for (int c = 0; c < 4; ++c) {
            const float* pa = Qb + (size_t)ar * HD + c * 16 + acl * 8;
            float4 r0 = *(const float4*)pa;
            float4 r1 = *(const float4*)(pa + 4);
            float av[8] = {r0.x, r0.y, r0.z, r0.w, r1.x, r1.y, r1.z, r1.w};
#pragma unroll
            for (int i = 0; i < 8; ++i)
                Qf[c][swz(abase + (i & 3))][(i >> 2) * 2 + ahi] = f2tf32(av[i] * 0.125f);
        }
    }

    float Oacc[2][4][4] = {};
    float rmax[2][2] = {{-1e30f, -1e30f}, {-1e30f, -1e30f}};
    float rsum[2][2] = {{0.f, 0.f}, {0.f, 0.f}};

    // B-producer ids: 2 chunks per pass, 128 threads each
    int pch = tid >> 7, pt = tid & 127;
    int br = pt & 15, nb = pt >> 4;
    int bkk = br & 7, btig = bkk & 3, bjw = (br >> 3) * 2 + (bkk >> 2);

    for (int kt = 0; kt < 32; ++kt) {
        __syncthreads();   // prev PV done reading Vf/Pf
        // ---- K tile: B[k=d][n=kv] from KT (row-major, ld=SEQN) ----
        // ---- V tile: B[k=kv][n=hd] from Vb (row-major, ld=HD)  ----
#pragma unroll
        for (int pp = 0; pp < 2; ++pp) {
            int ch = pp * 2 + pch;
            const float* ps = KT + (size_t)(ch * 16 + br) * SEQN + kt * 64 + nb * 8;
            float4 r0 = *(const float4*)ps;
            float4 r1 = *(const float4*)(ps + 4);
            float bv[8] = {r0.x, r0.y, r0.z, r0.w, r1.x, r1.y, r1.z, r1.w};
#pragma unroll
            for (int i = 0; i < 8; ++i)
                Kf[ch][swz((uint32_t)(nb * 32 + i * 4 + btig))][bjw] = f2tf32(bv[i]);
            const float* pv = Vb + (size_t)(kt * 64 + ch * 16 + br) * HD + nb * 8;
            float4 v0 = *(const float4*)pv;
            float4 v1 = *(const float4*)(pv + 4);
            float vv[8] = {v0.x, v0.y, v0.z, v0.w, v1.x, v1.y, v1.z, v1.w};
#pragma unroll
            for (int i = 0; i < 8; ++i)
                Vf[ch][swz((uint32_t)(nb * 32 + i * 4 + btig))][bjw] = f2tf32(vv[i]);
        }
        __syncthreads();

        // ---- S = (Q*scale) @ K^T ----
        float S[2][4][4] = {};
#pragma unroll
        for (int c = 0; c < 4; ++c) {
            uint32_t af[2][2][4];
#pragma unroll
            for (int mt = 0; mt < 2; ++mt) {
                uint32_t gb = (uint32_t)(((wm * 2 + mt) * 2) * 32 + lane);
                uint4 f0 = *(const uint4*)Qf[c][swz(gb)];
                uint4 f1 = *(const uint4*)Qf[c][swz(gb + 32)];
                af[mt][0][0] = f0.x; af[mt][0][1] = f0.y; af[mt][0][2] = f0.z; af[mt][0][3] = f0.w;
                af[mt][1][0] = f1.x; af[mt][1][1] = f1.y; af[mt][1][2] = f1.z; af[mt][1][3] = f1.w;
            }
#pragma unroll
            for (int nt = 0; nt < 4; ++nt) {
                uint4 fb = *(const uint4*)Kf[c][swz((uint32_t)((wn * 4 + nt) * 32 + lane))];
#pragma unroll
                for (int mt = 0; mt < 2; ++mt) {
                    mma_tf32(S[mt][nt], af[mt][0], fb.x, fb.y);
                    mma_tf32(S[mt][nt], af[mt][1], fb.z, fb.w);
                }
            }
        }

        // ---- online softmax ----
        float tmax[2][2], nm[2][2], corr[2][2], tsum[2][2];
#pragma unroll
        for (int mt = 0; mt < 2; ++mt)
#pragma unroll
            for (int hi = 0; hi < 2; ++hi) {
                float v = fmaxf(S[mt][0][hi * 2], S[mt][0][hi * 2 + 1]);
#pragma unroll
                for (int nt = 1; nt < 4; ++nt)
                    v = fmaxf(v, fmaxf(S[mt][nt][hi * 2], S[mt][nt][hi * 2 + 1]));
                v = fmaxf(v, __shfl_xor_sync(0xffffffffu, v, 1));
                v = fmaxf(v, __shfl_xor_sync(0xffffffffu, v, 2));
                tmax[mt][hi] = v;
            }
        if (tig == 0) {
#pragma unroll
            for (int mt = 0; mt < 2; ++mt)
#pragma unroll
                for (int hi = 0; hi < 2; ++hi)
                    smax[wn * 128 + wm * 32 + mt * 16 + hi * 8 + g] = tmax[mt][hi];
        }
        __syncthreads();
#pragma unroll
        for (int mt = 0; mt < 2; ++mt)
#pragma unroll
            for (int hi = 0; hi < 2; ++hi) {
                int r = wm * 32 + mt * 16 + hi * 8 + g;
                float tm = fmaxf(tmax[mt][hi], smax[(wn ^ 1) * 128 + r]);
                float n2 = fmaxf(rmax[mt][hi], tm);
                nm[mt][hi] = n2;
                corr[mt][hi] = __expf(rmax[mt][hi] - n2);
                rmax[mt][hi] = n2;
                tsum[mt][hi] = 0.f;
            }
        // exp, write P (A-frag), partial sums, scale O
#pragma unroll
        for (int mt = 0; mt < 2; ++mt)
#pragma unroll
            for (int nt = 0; nt < 4; ++nt)
#pragma unroll
                for (int hi = 0; hi < 2; ++hi)
#pragma unroll
                    for (int e = 0; e < 2; ++e) {
                        float p = __expf(S[mt][nt][hi * 2 + e] - nm[mt][hi]);
                        tsum[mt][hi] += p;
                        int col = wn * 32 + nt * 8 + 2 * tig + e;
                        int kp = col & 15;
                        uint32_t grp = (uint32_t)(((wm * 2 + mt) * 2 + (kp >> 3)) * 32
                                                  + g * 4 + (kp & 3));
                        Pf[col >> 4][swz(grp)][((kp >> 2) & 1) * 2 + hi] = f2tf32(p);
                    }
#pragma unroll
        for (int mt = 0; mt < 2; ++mt)
#pragma unroll
            for (int hi = 0; hi < 2; ++hi) {
                float v = tsum[mt][hi];
                v += __shfl_xor_sync(0xffffffffu, v, 1);
                v += __shfl_xor_sync(0xffffffffu, v, 2);
                tsum[mt][hi] = v;
#pragma unroll
                for (int nt = 0; nt < 4; ++nt) {
                    Oacc[mt][nt][hi * 2 + 0] *= corr[mt][hi];
                    Oacc[mt][nt][hi * 2 + 1] *= corr[mt][hi];
                }
            }
        if (tig == 0) {
#pragma unroll
            for (int mt = 0; mt < 2; ++mt)
#pragma unroll
                for (int hi = 0; hi < 2; ++hi)
                    ssum[wn * 128 + wm * 32 + mt * 16 + hi * 8 + g] = tsum[mt][hi];
        }
        __syncthreads();
#pragma unroll
        for (int mt = 0; mt < 2; ++mt)
#pragma unroll
            for (int hi = 0; hi < 2; ++hi) {
                int r = wm * 32 + mt * 16 + hi * 8 + g;
                rsum[mt][hi] = rsum[mt][hi] * corr[mt][hi]
                             + tsum[mt][hi] + ssum[(wn ^ 1) * 128 + r];
            }

        // ---- O += P @ V ----
#pragma unroll
        for (int c = 0; c < 4; ++c) {
            uint32_t af[2][2][4];
#pragma unroll
            for (int mt = 0; mt < 2; ++mt) {
                uint32_t gb = (uint32_t)(((wm * 2 + mt) * 2) * 32 + lane);
                uint4 f0 = *(const uint4*)Pf[c][swz(gb)];
                uint4 f1 = *(const uint4*)Pf[c][swz(gb + 32)];
                af[mt][0][0] = f0.x; af[mt][0][1] = f0.y; af[mt][0][2] = f0.z; af[mt][0][3] = f0.w;
                af[mt][1][0] = f1.x; af[mt][1][1] = f1.y; af[mt][1][2] = f1.z; af[mt][1][3] = f1.w;
            }
#pragma unroll
            for (int nt = 0; nt < 4; ++nt) {
                uint4 fb = *(const uint4*)Vf[c][swz((uint32_t)((wn * 4 + nt) * 32 + lane))];
#pragma unroll
                for (int mt = 0; mt < 2; ++mt) {
                    mma_tf32(Oacc[mt][nt], af[mt][0], fb.x, fb.y);
                    mma_tf32(Oacc[mt][nt], af[mt][1], fb.z, fb.w);
                }
            }
        }
    }

    // ---- epilogue: normalize + write g_m ----
    size_t rowbase = (size_t)dir * ROWS_HALF + (size_t)b * SEQN + (size_t)qt * 128;
#pragma unroll
    for (int mt = 0; mt < 2; ++mt)
#pragma unroll
        for (int hi = 0; hi < 2; ++hi) {
            float inv = 1.0f / rsum[mt][hi];
            size_t row = rowbase + wm * 32 + mt * 16 + hi * 8 + g;
#pragma unroll
            for (int nt = 0; nt < 4; ++nt) {
                int col = wn * 32 + nt * 8 + 2 * tig;
                *(float2*)&g_m[row * DMODEL + h * HD + col] =
                    make_float2(Oacc[mt][nt][hi * 2 + 0] * inv,
                                Oacc[mt][nt][hi * 2 + 1] * inv);
            }
        }
}

// ---------------- kernel 5: layernorm + exact gelu (unchanged) ----------------
__global__ __launch_bounds__(128) void k_lngelu(const float* __restrict__ lns,
                                                const float* __restrict__ lnb) {
    __shared__ float red[4];
    int row = blockIdx.x;
    int t = threadIdx.x;
    float* yp = g_y + (size_t)row * 512 + t * 4;
    float4 v = *(float4*)yp;

    float s = v.x + v.y + v.z + v.w;
#pragma unroll
    for (int off = 16; off; off >>= 1) s += __shfl_xor_sync(0xffffffffu, s, off);
    if ((t & 31) == 0) red[t >> 5] = s;
    __syncthreads();
    float mean = (red[0] + red[1] + red[2] + red[3]) * (1.0f / 512.0f);

    float d0 = v.x - mean, d1 = v.y - mean, d2 = v.z - mean, d3 = v.w - mean;
    float ss = d0 * d0 + d1 * d1 + d2 * d2 + d3 * d3;
#pragma unroll
    for (int off = 16; off; off >>= 1) ss += __shfl_xor_sync(0xffffffffu, ss, off);
    __syncthreads();
    if ((t & 31) == 0) red[t >> 5] = ss;
    __syncthreads();
    float var = (red[0] + red[1] + red[2] + red[3]) * (1.0f / 512.0f);
    float rstd = rsqrtf(var + 1e-5f);

    int c = t * 4;
    float g0 = d0 * rstd * lns[c + 0] + lnb[c + 0];
    float g1 = d1 * rstd * lns[c + 1] + lnb[c + 1];
    float g2 = d2 * rstd * lns[c + 2] + lnb[c + 2];
    float g3 = d3 * rstd * lns[c + 3] + lnb[c + 3];
    const float is2 = 0.70710678118654752f;
    v.x = 0.5f * g0 * (1.0f + erff(g0 * is2));
    v.y = 0.5f * g1 * (1.0f + erff(g1 * is2));
    v.z = 0.5f * g2 * (1.0f + erff(g2 * is2));
    v.w = 0.5f * g3 * (1.0f + erff(g3 * is2));
    *(float4*)yp = v;
}

// ---------------- launch ----------------
extern "C" void kernel_launch(void* const* d_in, const int* in_sizes, int n_in,
                              void* d_out, int out_size) {
    const float* x0   = (const float*)d_in[0];
    const float* x1   = (const float*)d_in[1];
    const float* Wqk  = (const float*)d_in[2];
    const float* bqk  = (const float*)d_in[3];
    const float* Wv   = (const float*)d_in[4];
    const float* bv   = (const float*)d_in[5];
    const float* Wout = (const float*)d_in[6];
    const float* bout = (const float*)d_in[7];
    const float* W0   = (const float*)d_in[8];
    const float* b0   = (const float*)d_in[9];
    const float* lns  = (const float*)d_in[10];
    const float* lnb  = (const float*)d_in[11];
    const float* W3   = (const float*)d_in[12];
    const float* b3   = (const float*)d_in[13];
    float* out = (float*)d_out;

    cudaFuncSetAttribute(k_attn_mma, cudaFuncAttributeMaxDynamicSharedMemorySize,
                         ATTN_SMEM_BYTES);

    k_proj_mma   <<<dim3(4, 128), 256>>>(x0, x1, Wqk, bqk, Wv, bv);
    k_attn_mma   <<<dim3(16, 16, 2), 256, ATTN_SMEM_BYTES>>>();
    k_outproj_mma<<<dim3(2, 128), 256>>>(Wout, bout);
    k_ffn0_mma   <<<dim3(4, 128), 256>>>(x0, x1, W0, b0);
    k_lngelu     <<<ROWS_TOT, 128>>>(lns, lnb);
    k_ffn3_mma   <<<dim3(2, 128), 256>>>(x0, x1, W3, b3, out);
}

// round 14
// speedup vs baseline: 1.1624x; 1.1624x over previous
#include <cuda_runtime.h>
#include <cstdint>
#include <math.h>

// Problem constants
#define NB        4
#define SEQN      2048
#define DMODEL    256
#define HEADS     4
#define HD        64
#define ROWS_HALF 8192      // NB * SEQN
#define ROWS_TOT  16384     // 2 * NB * SEQN

// ---------------- scratch (no allocs allowed) ----------------
__device__ float g_qk [2 * NB * HEADS * SEQN * HD];  // [t][b][h][n][hd]
__device__ float g_qkT[2 * NB * HEADS * HD * SEQN];  // [t][b][h][hd][n]  (K^T for S-mma)
__device__ float g_v  [2 * NB * HEADS * SEQN * HD];  // [t][b][h][n][hd]
__device__ float g_m  [ROWS_TOT * DMODEL];           // attention out, head-merged
__device__ float g_mo [ROWS_TOT * DMODEL];           // after Wout
__device__ float g_y  [ROWS_TOT * 512];              // after W0 / LN / gelu

// ================= tf32 mma helpers (used by attention) =================
__device__ __forceinline__ uint32_t f2tf32(float x) {
    uint32_t r;
    asm("cvt.rna.tf32.f32 %0, %1;" : "=r"(r) : "f"(x));
    return r;
}
__device__ __forceinline__ void mma_tf32(float acc[4], const uint32_t a[4],
                                         uint32_t b0, uint32_t b1) {
    asm volatile(
        "mma.sync.aligned.m16n8k8.row.col.f32.tf32.tf32.f32 "
        "{%0,%1,%2,%3}, {%4,%5,%6,%7}, {%8,%9}, {%0,%1,%2,%3};\n"
        : "+f"(acc[0]), "+f"(acc[1]), "+f"(acc[2]), "+f"(acc[3])
        : "r"(a[0]), "r"(a[1]), "r"(a[2]), "r"(a[3]), "r"(b0), "r"(b1));
}
__device__ __forceinline__ uint32_t swz(uint32_t gidx) {
    return gidx ^ ((gidx >> 2) & 7u);
}

// ================= bf16 mma + ldmatrix helpers (GEMMs) =================
__device__ __forceinline__ uint32_t bf16x2(float lo, float hi) {
    uint32_t r;
    asm("cvt.rn.bf16x2.f32 %0, %1, %2;" : "=r"(r) : "f"(hi), "f"(lo));
    return r;
}
__device__ __forceinline__ void mma_bf16(float acc[4], const uint32_t a[4],
                                         uint32_t b0, uint32_t b1) {
    asm volatile(
        "mma.sync.aligned.m16n8k16.row.col.f32.bf16.bf16.f32 "
        "{%0,%1,%2,%3}, {%4,%5,%6,%7}, {%8,%9}, {%0,%1,%2,%3};\n"
        : "+f"(acc[0]), "+f"(acc[1]), "+f"(acc[2]), "+f"(acc[3])
        : "r"(a[0]), "r"(a[1]), "r"(a[2]), "r"(a[3]), "r"(b0), "r"(b1));
}
__device__ __forceinline__ void ldsm4(uint32_t r[4], uint32_t a) {
    asm volatile("ldmatrix.sync.aligned.m8n8.x4.shared.b16 {%0,%1,%2,%3}, [%4];"
        : "=r"(r[0]), "=r"(r[1]), "=r"(r[2]), "=r"(r[3]) : "r"(a));
}
__device__ __forceinline__ void ldsm4t(uint32_t r[4], uint32_t a) {
    asm volatile("ldmatrix.sync.aligned.m8n8.x4.trans.shared.b16 {%0,%1,%2,%3}, [%4];"
        : "=r"(r[0]), "=r"(r[1]), "=r"(r[2]), "=r"(r[3]) : "r"(a));
}
__device__ __forceinline__ uint32_t smaddr(const void* p) {
    return (uint32_t)__cvta_generic_to_shared(p);
}
// 16B-unit layouts. A tile: 128 rows x 32 bf16 (4 units/row).
// B tile: 32 k-rows x 128 bf16 (16 units/row). XOR spreads banks:
// ldmatrix phases conflict-free, producer STS.128 <=2-way.
__device__ __forceinline__ int auA(int row, int u) {
    return ((row >> 3) << 5) + (u << 3) + ((row & 7) ^ u);
}
__device__ __forceinline__ int buB(int k, int u) {
    return (k << 4) + (u ^ (k & 7));
}

__device__ __forceinline__ void sts_stage(uint32_t* A, uint32_t* B,
    const float4* pa, const float4* pb, int ar, int acl, int brr, int ub)
{
    *(uint4*)&A[auA(ar, acl * 2) * 4] = make_uint4(
        bf16x2(pa[0].x, pa[0].y), bf16x2(pa[0].z, pa[0].w),
        bf16x2(pa[1].x, pa[1].y), bf16x2(pa[1].z, pa[1].w));
    *(uint4*)&A[auA(ar, acl * 2 + 1) * 4] = make_uint4(
        bf16x2(pa[2].x, pa[2].y), bf16x2(pa[2].z, pa[2].w),
        bf16x2(pa[3].x, pa[3].y), bf16x2(pa[3].z, pa[3].w));
    *(uint4*)&B[buB(brr, ub) * 4] = make_uint4(
        bf16x2(pb[0].x, pb[0].y), bf16x2(pb[0].z, pb[0].w),
        bf16x2(pb[1].x, pb[1].y), bf16x2(pb[1].z, pb[1].w));
    *(uint4*)&B[buB(brr, ub + 1) * 4] = make_uint4(
        bf16x2(pb[2].x, pb[2].y), bf16x2(pb[2].z, pb[2].w),
        bf16x2(pb[3].x, pb[3].y), bf16x2(pb[3].z, pb[3].w));
}

// ================= bf16 GEMM mainloop =================
// C(128x128) = A(128xK) @ W(Kx128-slice). Chunk BK=32, 256 thr, 8 warps 4Mx2N.
// acc[2][8][4] identical layout to tf32 version (epilogues unchanged).
__device__ __forceinline__ void gemm_bf16(
    uint32_t (*Asm)[2048], uint32_t (*Bsm)[2048],
    const float* A0, int lda0, const float* A1, int lda1, int splitc,
    const float* Bw, int ldb, int n0, int NC, float acc[2][8][4])
{
    int tid = threadIdx.x, lane = tid & 31;
    int wid = tid >> 5, wm = wid & 3, wn = wid >> 2;
    int ar = tid >> 1, acl = tid & 1;          // A producer: row, k-half(16 floats)
    int brr = tid >> 3, ub = (tid & 7) * 2;    // B producer: k-row, unit base
    int lrow = ((lane >> 3) & 1) * 8 + (lane & 7);
    int lhi  = lane >> 4;

    float4 pa[4], pb[4];
    {
        const float* Ab = (0 < splitc) ? A0 : A1;
        int lda = (0 < splitc) ? lda0 : lda1;
        const float* p = Ab + (size_t)ar * lda + acl * 16;
        pa[0] = ((const float4*)p)[0]; pa[1] = ((const float4*)p)[1];
        pa[2] = ((const float4*)p)[2]; pa[3] = ((const float4*)p)[3];
        const float* q = Bw + (size_t)brr * ldb + n0 + ub * 8;
        pb[0] = ((const float4*)q)[0]; pb[1] = ((const float4*)q)[1];
        pb[2] = ((const float4*)q)[2]; pb[3] = ((const float4*)q)[3];
    }
    sts_stage(Asm[0], Bsm[0], pa, pb, ar, acl, brr, ub);
    __syncthreads();

    for (int c = 0; c < NC; ++c) {
        int cur = c & 1;
        bool more = (c + 1 < NC);
        if (more) {
            int cn = c + 1;
            const float* Ab; int lda;
            if (cn < splitc) { Ab = A0 + (size_t)cn * 32; lda = lda0; }
            else             { Ab = A1 + (size_t)(cn - splitc) * 32; lda = lda1; }
            const float* p = Ab + (size_t)ar * lda + acl * 16;
            pa[0] = ((const float4*)p)[0]; pa[1] = ((const float4*)p)[1];
            pa[2] = ((const float4*)p)[2]; pa[3] = ((const float4*)p)[3];
            const float* q = Bw + (size_t)(cn * 32 + brr) * ldb + n0 + ub * 8;
            pb[0] = ((const float4*)q)[0]; pb[1] = ((const float4*)q)[1];
            pb[2] = ((const float4*)q)[2]; pb[3] = ((const float4*)q)[3];
        }
        uint32_t af[2][2][4];
#pragma unroll
        for (int mt = 0; mt < 2; ++mt)
#pragma unroll
            for (int ks = 0; ks < 2; ++ks)
                ldsm4(af[mt][ks],
                      smaddr(&Asm[cur][auA(wm * 32 + mt * 16 + lrow, ks * 2 + lhi) * 4]));
#pragma unroll
        for (int ks = 0; ks < 2; ++ks)
#pragma unroll
            for (int p2 = 0; p2 < 4; ++p2) {
                uint32_t bf[4];
                ldsm4t(bf, smaddr(&Bsm[cur][buB(ks * 16 + lrow, wn * 8 + p2 * 2 + lhi) * 4]));
#pragma unroll
                for (int mt = 0; mt < 2; ++mt) {
                    mma_bf16(acc[mt][p2 * 2 + 0], af[mt][ks], bf[0], bf[1]);
                    mma_bf16(acc[mt][p2 * 2 + 1], af[mt][ks], bf[2], bf[3]);
                }
            }
        if (more) sts_stage(Asm[cur ^ 1], Bsm[cur ^ 1], pa, pb, ar, acl, brr, ub);
        __syncthreads();
    }
}

#define MMA_EPI_IDS                                       \
    int tid = threadIdx.x;                                \
    int lane = tid & 31, g = lane >> 2, tig = lane & 3;   \
    int wid = tid >> 5, wm = wid & 3, wn = wid >> 2;      \
    (void)lane;

// ---------------- kernel 1: qk / v projection (+ K^T write) ----------------
__global__ __launch_bounds__(256) void k_proj_mma(
    const float* __restrict__ x0, const float* __restrict__ x1,
    const float* __restrict__ Wqk, const float* __restrict__ bqk,
    const float* __restrict__ Wv,  const float* __restrict__ bv)
{
    __shared__ __align__(16) uint32_t As[2][2048];
    __shared__ __align__(16) uint32_t Bs[2][2048];
    int m0  = blockIdx.y * 128;
    int n0g = blockIdx.x * 128;           // 0..511
    bool isv = (n0g >= 256);
    const float* Bw   = isv ? Wv : Wqk;
    const float* bias = isv ? bv : bqk;
    int n0 = n0g & 255;
    const float* A0 = (m0 < ROWS_HALF) ? (x0 + (size_t)m0 * DMODEL)
                                       : (x1 + (size_t)(m0 - ROWS_HALF) * DMODEL);
    float acc[2][8][4] = {};
    gemm_bf16(As, Bs, A0, DMODEL, A0, DMODEL, 1 << 20, Bw, DMODEL, n0, 8, acc);

    MMA_EPI_IDS;
    int t = (m0 >= ROWS_HALF);
    int base = m0 - t * ROWS_HALF;
    int bb = base >> 11;
    float* dst = isv ? g_v : g_qk;
    size_t hb = (((size_t)t * NB + bb) * HEADS) * (size_t)SEQN * HD;
#pragma unroll
    for (int mt = 0; mt < 2; ++mt) {
        int r   = m0 + wm * 32 + mt * 16 + g;
        int nn0 = (r - t * ROWS_HALF) & 2047;
#pragma unroll
        for (int nt = 0; nt < 8; ++nt) {
            int c = n0 + wn * 64 + nt * 8 + 2 * tig;
            int h = c >> 6, hd = c & 63;
            float b0v = bias[c], b1v = bias[c + 1];
            float va = acc[mt][nt][0] + b0v, vb = acc[mt][nt][1] + b1v;
            float vc = acc[mt][nt][2] + b0v, vd = acc[mt][nt][3] + b1v;
            size_t d0 = hb + ((size_t)h * SEQN + nn0) * HD + hd;
            size_t d1 = hb + ((size_t)h * SEQN + nn0 + 8) * HD + hd;
            *(float2*)&dst[d0] = make_float2(va, vb);
            *(float2*)&dst[d1] = make_float2(vc, vd);
            if (!isv) {
                size_t tb = ((((size_t)t * NB + bb) * HEADS + h) * HD + hd) * (size_t)SEQN;
                g_qkT[tb + nn0]            = va;
                g_qkT[tb + SEQN + nn0]     = vb;
                g_qkT[tb + nn0 + 8]        = vc;
                g_qkT[tb + SEQN + nn0 + 8] = vd;
            }
        }
    }
}

// ---------------- kernel 3: mo = m @ Wout + bout ----------------
__global__ __launch_bounds__(256) void k_outproj_mma(
    const float* __restrict__ Wout, const float* __restrict__ bout)
{
    __shared__ __align__(16) uint32_t As[2][2048];
    __shared__ __align__(16) uint32_t Bs[2][2048];
    int m0 = blockIdx.y * 128;
    int n0 = blockIdx.x * 128;
    const float* A0 = g_m + (size_t)m0 * DMODEL;
    float acc[2][8][4] = {};
    gemm_bf16(As, Bs, A0, DMODEL, A0, DMODEL, 1 << 20, Wout, DMODEL, n0, 8, acc);

    MMA_EPI_IDS;
#pragma unroll
    for (int mt = 0; mt < 2; ++mt) {
        int r = m0 + wm * 32 + mt * 16 + g;
#pragma unroll
        for (int nt = 0; nt < 8; ++nt) {
            int c = n0 + wn * 64 + nt * 8 + 2 * tig;
            float b0v = bout[c], b1v = bout[c + 1];
            *(float2*)&g_mo[(size_t)r * DMODEL + c] =
                make_float2(acc[mt][nt][0] + b0v, acc[mt][nt][1] + b1v);
            *(float2*)&g_mo[(size_t)(r + 8) * DMODEL + c] =
                make_float2(acc[mt][nt][2] + b0v, acc[mt][nt][3] + b1v);
        }
    }
}

// ---------------- kernel 4: y = [x | mo] @ W0 + b0 ----------------
__global__ __launch_bounds__(256) void k_ffn0_mma(
    const float* __restrict__ x0, const float* __restrict__ x1,
    const float* __restrict__ W0, const float* __restrict__ b0)
{
    __shared__ __align__(16) uint32_t As[2][2048];
    __shared__ __align__(16) uint32_t Bs[2][2048];
    int m0 = blockIdx.y * 128;
    int n0 = blockIdx.x * 128;   // 0..511
    const float* ax = (m0 < ROWS_HALF) ? (x0 + (size_t)m0 * DMODEL)
                                       : (x1 + (size_t)(m0 - ROWS_HALF) * DMODEL);
    const float* am = g_mo + (size_t)m0 * DMODEL;
    float acc[2][8][4] = {};
    gemm_bf16(As, Bs, ax, DMODEL, am, DMODEL, 8, W0, 512, n0, 16, acc);

    MMA_EPI_IDS;
#pragma unroll
    for (int mt = 0; mt < 2; ++mt) {
        int r = m0 + wm * 32 + mt * 16 + g;
#pragma unroll
        for (int nt = 0; nt < 8; ++nt) {
            int c = n0 + wn * 64 + nt * 8 + 2 * tig;
            float b0v = b0[c], b1v = b0[c + 1];
            *(float2*)&g_y[(size_t)r * 512 + c] =
                make_float2(acc[mt][nt][0] + b0v, acc[mt][nt][1] + b1v);
            *(float2*)&g_y[(size_t)(r + 8) * 512 + c] =
                make_float2(acc[mt][nt][2] + b0v, acc[mt][nt][3] + b1v);
        }
    }
}

// ---------------- kernel 6: out = x + y @ W3 + b3 ----------------
__global__ __launch_bounds__(256) void k_ffn3_mma(
    const float* __restrict__ x0, const float* __restrict__ x1,
    const float* __restrict__ W3, const float* __restrict__ b3,
    float* __restrict__ out)
{
    __shared__ __align__(16) uint32_t As[2][2048];
    __shared__ __align__(16) uint32_t Bs[2][2048];
    int m0 = blockIdx.y * 128;
    int n0 = blockIdx.x * 128;   // 0..255
    const float* A0 = g_y + (size_t)m0 * 512;
    float acc[2][8][4] = {};
    gemm_bf16(As, Bs, A0, 512, A0, 512, 1 << 20, W3, DMODEL, n0, 16, acc);

    MMA_EPI_IDS;
    const float* xb = (m0 < ROWS_HALF) ? (x0 + (size_t)m0 * DMODEL)
                                       : (x1 + (size_t)(m0 - ROWS_HALF) * DMODEL);
#pragma unroll
    for (int mt = 0; mt < 2; ++mt) {
        int r  = m0 + wm * 32 + mt * 16 + g;
        int rl = wm * 32 + mt * 16 + g;
#pragma unroll
        for (int nt = 0; nt < 8; ++nt) {
            int c = n0 + wn * 64 + nt * 8 + 2 * tig;
            float b0v = b3[c], b1v = b3[c + 1];
            float2 xv0 = *(const float2*)(xb + (size_t)rl * DMODEL + c);
            float2 xv1 = *(const float2*)(xb + (size_t)(rl + 8) * DMODEL + c);
            *(float2*)&out[(size_t)r * DMODEL + c] =
                make_float2(acc[mt][nt][0] + b0v + xv0.x, acc[mt][nt][1] + b1v + xv0.y);
            *(float2*)&out[(size_t)(r + 8) * DMODEL + c] =
                make_float2(acc[mt][nt][2] + b0v + xv1.x, acc[mt][nt][3] + b1v + xv1.y);
        }
    }
}

// ---------------- kernel 2: tf32 mma flash attention (passing R12) ----------
#define ATTN_SMEM_WORDS 25088
#define ATTN_SMEM_BYTES (ATTN_SMEM_WORDS * 4)

__global__ __launch_bounds__(256) void k_attn_mma() {
    extern __shared__ uint32_t sm[];
    uint32_t (*Qf)[512][4] = (uint32_t(*)[512][4])(sm);
    uint32_t (*Kf)[256][4] = (uint32_t(*)[256][4])(sm + 8192);
    uint32_t (*Vf)[256][4] = (uint32_t(*)[256][4])(sm + 12288);
    uint32_t (*Pf)[512][4] = (uint32_t(*)[512][4])(sm + 16384);
    float* smax = (float*)(sm + 24576);   // [2][128]
    float* ssum = (float*)(sm + 24832);   // [2][128]

    int qt = blockIdx.x, bh = blockIdx.y, dir = blockIdx.z;
    int b = bh >> 2, h = bh & 3, kvd = 1 - dir;

    const float* Qb = g_qk  + (((size_t)dir * NB + b) * HEADS + h) * (size_t)SEQN * HD
                            + (size_t)qt * 128 * HD;
    const float* KT = g_qkT + (((size_t)kvd * NB + b) * HEADS + h) * (size_t)HD * SEQN;
    const float* Vb = g_v   + (((size_t)kvd * NB + b) * HEADS + h) * (size_t)SEQN * HD;

    int tid = threadIdx.x, lane = tid & 31, g = lane >> 2, tig = tid & 3;
    int wid = tid >> 5, wm = wid & 3, wn = wid >> 2;

    {
        int ar = tid >> 1, acl = tid & 1;
        int amt = ar >> 4, amr = ar & 15, ag = amr & 7, ahi = amr >> 3;
        uint32_t abase = (uint32_t)((amt * 2 + acl) * 32 + ag * 4);
#pragma unroll
        for (int c = 0; c < 4; ++c) {
            const float* pa = Qb + (size_t)ar * HD + c * 16 + acl * 8;
            float4 r0 = *(const float4*)pa;
            float4 r1 = *(const float4*)(pa + 4);
            float av[8] = {r0.x, r0.y, r0.z, r0.w, r1.x, r1.y, r1.z, r1.w};
#pragma unroll
            for (int i = 0; i < 8; ++i)
                Qf[c][swz(abase + (i & 3))][(i >> 2) * 2 + ahi] = f2tf32(av[i] * 0.125f);
        }
    }

    float Oacc[2][4][4] = {};
    float rmax[2][2] = {{-1e30f, -1e30f}, {-1e30f, -1e30f}};
    float rsum[2][2] = {{0.f, 0.f}, {0.f, 0.f}};

    int pch = tid >> 7, pt = tid & 127;
    int br = pt & 15, nb = pt >> 4;
    int bkk = br & 7, btig = bkk & 3, bjw = (br >> 3) * 2 + (bkk >> 2);

    for (int kt = 0; kt < 32; ++kt) {
        __syncthreads();
#pragma unroll
        for (int pp = 0; pp < 2; ++pp) {
            int ch = pp * 2 + pch;
            const float* ps = KT + (size_t)(ch * 16 + br) * SEQN + kt * 64 + nb * 8;
            float4 r0 = *(const float4*)ps;
            float4 r1 = *(const float4*)(ps + 4);
            float bv[8] = {r0.x, r0.y, r0.z, r0.w, r1.x, r1.y, r1.z, r1.w};
#pragma unroll
            for (int i = 0; i < 8; ++i)
                Kf[ch][swz((uint32_t)(nb * 32 + i * 4 + btig))][bjw] = f2tf32(bv[i]);
            const float* pv = Vb + (size_t)(kt * 64 + ch * 16 + br) * HD + nb * 8;
            float4 v0 = *(const float4*)pv;
            float4 v1 = *(const float4*)(pv + 4);
            float vv[8] = {v0.x, v0.y, v0.z, v0.w, v1.x, v1.y, v1.z, v1.w};
#pragma unroll
            for (int i = 0; i < 8; ++i)
                Vf[ch][swz((uint32_t)(nb * 32 + i * 4 + btig))][bjw] = f2tf32(vv[i]);
        }
        __syncthreads();

        float S[2][4][4] = {};
#pragma unroll
        for (int c = 0; c < 4; ++c) {
            uint32_t af[2][2][4];
#pragma unroll
            for (int mt = 0; mt < 2; ++mt) {
                uint32_t gb = (uint32_t)(((wm * 2 + mt) * 2) * 32 + lane);
                uint4 f0 = *(const uint4*)Qf[c][swz(gb)];
                uint4 f1 = *(const uint4*)Qf[c][swz(gb + 32)];
                af[mt][0][0] = f0.x; af[mt][0][1] = f0.y; af[mt][0][2] = f0.z; af[mt][0][3] = f0.w;
                af[mt][1][0] = f1.x; af[mt][1][1] = f1.y; af[mt][1][2] = f1.z; af[mt][1][3] = f1.w;
            }
#pragma unroll
            for (int nt = 0; nt < 4; ++nt) {
                uint4 fb = *(const uint4*)Kf[c][swz((uint32_t)((wn * 4 + nt) * 32 + lane))];
#pragma unroll
                for (int mt = 0; mt < 2; ++mt) {
                    mma_tf32(S[mt][nt], af[mt][0], fb.x, fb.y);
                    mma_tf32(S[mt][nt], af[mt][1], fb.z, fb.w);
                }
            }
        }

        float tmax[2][2], nm[2][2], corr[2][2], tsum[2][2];
#pragma unroll
        for (int mt = 0; mt < 2; ++mt)
#pragma unroll
            for (int hi = 0; hi < 2; ++hi) {
                float v = fmaxf(S[mt][0][hi * 2], S[mt][0][hi * 2 + 1]);
#pragma unroll
                for (int nt = 1; nt < 4; ++nt)
                    v = fmaxf(v, fmaxf(S[mt][nt][hi * 2], S[mt][nt][hi * 2 + 1]));
                v = fmaxf(v, __shfl_xor_sync(0xffffffffu, v, 1));
                v = fmaxf(v, __shfl_xor_sync(0xffffffffu, v, 2));
                tmax[mt][hi] = v;
            }
        if (tig == 0) {
#pragma unroll
            for (int mt = 0; mt < 2; ++mt)
#pragma unroll
                for (int hi = 0; hi < 2; ++hi)
                    smax[wn * 128 + wm * 32 + mt * 16 + hi * 8 + g] = tmax[mt][hi];
        }
        __syncthreads();
#pragma unroll
        for (int mt = 0; mt < 2; ++mt)
#pragma unroll
            for (int hi = 0; hi < 2; ++hi) {
                int r = wm * 32 + mt * 16 + hi * 8 + g;
                float tm = fmaxf(tmax[mt][hi], smax[(wn ^ 1) * 128 + r]);
                float n2 = fmaxf(rmax[mt][hi], tm);
                nm[mt][hi] = n2;
                corr[mt][hi] = __expf(rmax[mt][hi] - n2);
                rmax[mt][hi] = n2;
                tsum[mt][hi] = 0.f;
            }
#pragma unroll
        for (int mt = 0; mt < 2; ++mt)
#pragma unroll
            for (int nt = 0; nt < 4; ++nt)
#pragma unroll
                for (int hi = 0; hi < 2; ++hi)
#pragma unroll
                    for (int e = 0; e < 2; ++e) {
                        float p = __expf(S[mt][nt][hi * 2 + e] - nm[mt][hi]);
                        tsum[mt][hi] += p;
                        int col = wn * 32 + nt * 8 + 2 * tig + e;
                        int kp = col & 15;
                        uint32_t grp = (uint32_t)(((wm * 2 + mt) * 2 + (kp >> 3)) * 32
                                                  + g * 4 + (kp & 3));
                        Pf[col >> 4][swz(grp)][((kp >> 2) & 1) * 2 + hi] = f2tf32(p);
                    }
#pragma unroll
        for (int mt = 0; mt < 2; ++mt)
#pragma unroll
            for (int hi = 0; hi < 2; ++hi) {
                float v = tsum[mt][hi];
                v += __shfl_xor_sync(0xffffffffu, v, 1);
                v += __shfl_xor_sync(0xffffffffu, v, 2);
                tsum[mt][hi] = v;
#pragma unroll
                for (int nt = 0; nt < 4; ++nt) {
                    Oacc[mt][nt][hi * 2 + 0] *= corr[mt][hi];
                    Oacc[mt][nt][hi * 2 + 1] *= corr[mt][hi];
                }
            }
        if (tig == 0) {
#pragma unroll
            for (int mt = 0; mt < 2; ++mt)
#pragma unroll
                for (int hi = 0; hi < 2; ++hi)
                    ssum[wn * 128 + wm * 32 + mt * 16 + hi * 8 + g] = tsum[mt][hi];
        }
        __syncthreads();
#pragma unroll
        for (int mt = 0; mt < 2; ++mt)
#pragma unroll
            for (int hi = 0; hi < 2; ++hi) {
                int r = wm * 32 + mt * 16 + hi * 8 + g;
                rsum[mt][hi] = rsum[mt][hi] * corr[mt][hi]
                             + tsum[mt][hi] + ssum[(wn ^ 1) * 128 + r];
            }

#pragma unroll
        for (int c = 0; c < 4; ++c) {
            uint32_t af[2][2][4];
#pragma unroll
            for (int mt = 0; mt < 2; ++mt) {
                uint32_t gb = (uint32_t)(((wm * 2 + mt) * 2) * 32 + lane);
                uint4 f0 = *(const uint4*)Pf[c][swz(gb)];
                uint4 f1 = *(const uint4*)Pf[c][swz(gb + 32)];
                af[mt][0][0] = f0.x; af[mt][0][1] = f0.y; af[mt][0][2] = f0.z; af[mt][0][3] = f0.w;
                af[mt][1][0] = f1.x; af[mt][1][1] = f1.y; af[mt][1][2] = f1.z; af[mt][1][3] = f1.w;
            }
#pragma unroll
            for (int nt = 0; nt < 4; ++nt) {
                uint4 fb = *(const uint4*)Vf[c][swz((uint32_t)((wn * 4 + nt) * 32 + lane))];
#pragma unroll
                for (int mt = 0; mt < 2; ++mt) {
                    mma_tf32(Oacc[mt][nt], af[mt][0], fb.x, fb.y);
                    mma_tf32(Oacc[mt][nt], af[mt][1], fb.z, fb.w);
                }
            }
        }
    }

    size_t rowbase = (size_t)dir * ROWS_HALF + (size_t)b * SEQN + (size_t)qt * 128;
#pragma unroll
    for (int mt = 0; mt < 2; ++mt)
#pragma unroll
        for (int hi = 0; hi < 2; ++hi) {
            float inv = 1.0f / rsum[mt][hi];
            size_t row = rowbase + wm * 32 + mt * 16 + hi * 8 + g;
#pragma unroll
            for (int nt = 0; nt < 4; ++nt) {
                int col = wn * 32 + nt * 8 + 2 * tig;
                *(float2*)&g_m[row * DMODEL + h * HD + col] =
                    make_float2(Oacc[mt][nt][hi * 2 + 0] * inv,
                                Oacc[mt][nt][hi * 2 + 1] * inv);
            }
        }
}

// ---------------- kernel 5: layernorm + exact gelu ----------------
__global__ __launch_bounds__(128) void k_lngelu(const float* __restrict__ lns,
                                                const float* __restrict__ lnb) {
    __shared__ float red[4];
    int row = blockIdx.x;
    int t = threadIdx.x;
    float* yp = g_y + (size_t)row * 512 + t * 4;
    float4 v = *(float4*)yp;

    float s = v.x + v.y + v.z + v.w;
#pragma unroll
    for (int off = 16; off; off >>= 1) s += __shfl_xor_sync(0xffffffffu, s, off);
    if ((t & 31) == 0) red[t >> 5] = s;
    __syncthreads();
    float mean = (red[0] + red[1] + red[2] + red[3]) * (1.0f / 512.0f);

    float d0 = v.x - mean, d1 = v.y - mean, d2 = v.z - mean, d3 = v.w - mean;
    float ss = d0 * d0 + d1 * d1 + d2 * d2 + d3 * d3;
#pragma unroll
    for (int off = 16; off; off >>= 1) ss += __shfl_xor_sync(0xffffffffu, ss, off);
    __syncthreads();
    if ((t & 31) == 0) red[t >> 5] = ss;
    __syncthreads();
    float var = (red[0] + red[1] + red[2] + red[3]) * (1.0f / 512.0f);
    float rstd = rsqrtf(var + 1e-5f);

    int c = t * 4;
    float g0 = d0 * rstd * lns[c + 0] + lnb[c + 0];
    float g1 = d1 * rstd * lns[c + 1] + lnb[c + 1];
    float g2 = d2 * rstd * lns[c + 2] + lnb[c + 2];
    float g3 = d3 * rstd * lns[c + 3] + lnb[c + 3];
    const float is2 = 0.70710678118654752f;
    v.x = 0.5f * g0 * (1.0f + erff(g0 * is2));
    v.y = 0.5f * g1 * (1.0f + erff(g1 * is2));
    v.z = 0.5f * g2 * (1.0f + erff(g2 * is2));
    v.w = 0.5f * g3 * (1.0f + erff(g3 * is2));
    *(float4*)yp = v;
}

// ---------------- launch ----------------
extern "C" void kernel_launch(void* const* d_in, const int* in_sizes, int n_in,
                              void* d_out, int out_size) {
    const float* x0   = (const float*)d_in[0];
    const float* x1   = (const float*)d_in[1];
    const float* Wqk  = (const float*)d_in[2];
    const float* bqk  = (const float*)d_in[3];
    const float* Wv   = (const float*)d_in[4];
    const float* bv   = (const float*)d_in[5];
    const float* Wout = (const float*)d_in[6];
    const float* bout = (const float*)d_in[7];
    const float* W0   = (const float*)d_in[8];
    const float* b0   = (const float*)d_in[9];
    const float* lns  = (const float*)d_in[10];
    const float* lnb  = (const float*)d_in[11];
    const float* W3   = (const float*)d_in[12];
    const float* b3   = (const float*)d_in[13];
    float* out = (float*)d_out;

    cudaFuncSetAttribute(k_attn_mma, cudaFuncAttributeMaxDynamicSharedMemorySize,
                         ATTN_SMEM_BYTES);

    k_proj_mma   <<<dim3(4, 128), 256>>>(x0, x1, Wqk, bqk, Wv, bv);
    k_attn_mma   <<<dim3(16, 16, 2), 256, ATTN_SMEM_BYTES>>>();
    k_outproj_mma<<<dim3(2, 128), 256>>>(Wout, bout);
    k_ffn0_mma   <<<dim3(4, 128), 256>>>(x0, x1, W0, b0);
    k_lngelu     <<<ROWS_TOT, 128>>>(lns, lnb);
    k_ffn3_mma   <<<dim3(2, 128), 256>>>(x0, x1, W3, b3, out);
}

// round 16
// speedup vs baseline: 1.2485x; 1.0740x over previous
#include <cuda_runtime.h>
#include <cuda_bf16.h>
#include <cstdint>
#include <math.h>

#define NB        4
#define SEQN      2048
#define DMODEL    256
#define HEADS     4
#define HD        64
#define ROWS_HALF 8192
#define ROWS_TOT  16384

// ---------------- scratch (no allocs allowed) ----------------
__device__ float g_qk [2 * NB * HEADS * SEQN * HD];  // f32 (attention, tf32)
__device__ float g_qkT[2 * NB * HEADS * HD * SEQN];  // f32 K^T
__device__ float g_v  [2 * NB * HEADS * SEQN * HD];  // f32
__device__ float g_y  [ROWS_TOT * 512];              // f32 (LN input precision)
// bf16 operand mirrors (bit-identical cvt.rn of what the old code converted at STS)
__device__ __nv_bfloat16 c_x  [ROWS_TOT * DMODEL];
__device__ __nv_bfloat16 c_wqk[DMODEL * DMODEL];
__device__ __nv_bfloat16 c_wv [DMODEL * DMODEL];
__device__ __nv_bfloat16 c_wot[DMODEL * DMODEL];
__device__ __nv_bfloat16 c_w0 [512 * 512];
__device__ __nv_bfloat16 c_w3 [512 * DMODEL];
__device__ __nv_bfloat16 g_mb [ROWS_TOT * DMODEL];   // attention out (bf16)
__device__ __nv_bfloat16 g_mob[ROWS_TOT * DMODEL];   // after Wout (bf16)
__device__ __nv_bfloat16 g_y2 [ROWS_TOT * 512];      // post LN+gelu (bf16)

// ================= helpers =================
__device__ __forceinline__ uint32_t f2tf32(float x) {
    uint32_t r;
    asm("cvt.rna.tf32.f32 %0, %1;" : "=r"(r) : "f"(x));
    return r;
}
__device__ __forceinline__ void mma_tf32(float acc[4], const uint32_t a[4],
                                         uint32_t b0, uint32_t b1) {
    asm volatile(
        "mma.sync.aligned.m16n8k8.row.col.f32.tf32.tf32.f32 "
        "{%0,%1,%2,%3}, {%4,%5,%6,%7}, {%8,%9}, {%0,%1,%2,%3};\n"
        : "+f"(acc[0]), "+f"(acc[1]), "+f"(acc[2]), "+f"(acc[3])
        : "r"(a[0]), "r"(a[1]), "r"(a[2]), "r"(a[3]), "r"(b0), "r"(b1));
}
__device__ __forceinline__ uint32_t swz(uint32_t gidx) {
    return gidx ^ ((gidx >> 2) & 7u);
}
__device__ __forceinline__ uint32_t bf16x2(float lo, float hi) {
    uint32_t r;
    asm("cvt.rn.bf16x2.f32 %0, %1, %2;" : "=r"(r) : "f"(hi), "f"(lo));
    return r;
}
__device__ __forceinline__ void mma_bf16(float acc[4], const uint32_t a[4],
                                         uint32_t b0, uint32_t b1) {
    asm volatile(
        "mma.sync.aligned.m16n8k16.row.col.f32.bf16.bf16.f32 "
        "{%0,%1,%2,%3}, {%4,%5,%6,%7}, {%8,%9}, {%0,%1,%2,%3};\n"
        : "+f"(acc[0]), "+f"(acc[1]), "+f"(acc[2]), "+f"(acc[3])
        : "r"(a[0]), "r"(a[1]), "r"(a[2]), "r"(a[3]), "r"(b0), "r"(b1));
}
__device__ __forceinline__ void ldsm4(uint32_t r[4], uint32_t a) {
    asm volatile("ldmatrix.sync.aligned.m8n8.x4.shared.b16 {%0,%1,%2,%3}, [%4];"
        : "=r"(r[0]), "=r"(r[1]), "=r"(r[2]), "=r"(r[3]) : "r"(a));
}
__device__ __forceinline__ void ldsm4t(uint32_t r[4], uint32_t a) {
    asm volatile("ldmatrix.sync.aligned.m8n8.x4.trans.shared.b16 {%0,%1,%2,%3}, [%4];"
        : "=r"(r[0]), "=r"(r[1]), "=r"(r[2]), "=r"(r[3]) : "r"(a));
}
__device__ __forceinline__ uint32_t smaddr(const void* p) {
    return (uint32_t)__cvta_generic_to_shared(p);
}
__device__ __forceinline__ int auA(int row, int u) {
    return ((row >> 3) << 5) + (u << 3) + ((row & 7) ^ u);
}
__device__ __forceinline__ int buB(int k, int u) {
    return (k << 4) + (u ^ (k & 7));
}
#define CP16(sa, ga) \
    asm volatile("cp.async.cg.shared.global [%0], [%1], 16;" :: "r"(sa), "l"(ga))
#define CP_COMMIT() asm volatile("cp.async.commit_group;" ::: "memory")

// ================= bf16 GEMM mainloop: cp.async 3-stage =================
// C(128x128) = A(128xK) @ W(Kx128-slice). Chunk BK=32, 256 thr, 8 warps 4Mx2N.
__device__ __forceinline__ void stage_async(uint32_t* A, uint32_t* B,
    const __nv_bfloat16* Asrc, int lda, const __nv_bfloat16* Bsrc, int ldb, int tid)
{
    int ar = tid >> 1, u0 = (tid & 1) * 2;
    const char* ga = (const char*)(Asrc + (size_t)ar * lda + u0 * 8);
    CP16(smaddr(&A[auA(ar, u0) * 4]), ga);
    CP16(smaddr(&A[auA(ar, u0 + 1) * 4]), ga + 16);
    int brr = tid >> 3, ub = (tid & 7) * 2;
    const char* gb = (const char*)(Bsrc + (size_t)brr * ldb + ub * 8);
    CP16(smaddr(&B[buB(brr, ub) * 4]), gb);
    CP16(smaddr(&B[buB(brr, ub + 1) * 4]), gb + 16);
}

__device__ __forceinline__ void gemm_bf16(
    uint32_t (*Asm)[2048], uint32_t (*Bsm)[2048],
    const __nv_bfloat16* A0, int lda0, const __nv_bfloat16* A1, int lda1, int splitc,
    const __nv_bfloat16* Bw, int ldb, int n0, int NC, float acc[2][8][4])
{
    int tid = threadIdx.x, lane = tid & 31;
    int wid = tid >> 5, wm = wid & 3, wn = wid >> 2;
    int lrow = ((lane >> 3) & 1) * 8 + (lane & 7);
    int lhi  = lane >> 4;

    // prologue: stages 0,1
    {
        const __nv_bfloat16* Ab = (0 < splitc) ? A0 : A1;
        int lda = (0 < splitc) ? lda0 : lda1;
        stage_async(Asm[0], Bsm[0], Ab, lda, Bw + n0, ldb, tid);
        CP_COMMIT();
    }
    if (NC > 1) {
        const __nv_bfloat16* Ab; int lda;
        if (1 < splitc) { Ab = A0 + 32; lda = lda0; }
        else            { Ab = A1 + (1 - splitc) * 32; lda = lda1; }
        stage_async(Asm[1], Bsm[1], Ab, lda, Bw + (size_t)32 * ldb + n0, ldb, tid);
        CP_COMMIT();
    }

    for (int c = 0; c < NC; ++c) {
        if (c + 1 < NC) asm volatile("cp.async.wait_group 1;" ::: "memory");
        else            asm volatile("cp.async.wait_group 0;" ::: "memory");
        __syncthreads();
        int cur = c % 3;
        uint32_t af[2][2][4];
#pragma unroll
        for (int mt = 0; mt < 2; ++mt)
#pragma unroll
            for (int ks = 0; ks < 2; ++ks)
                ldsm4(af[mt][ks],
                      smaddr(&Asm[cur][auA(wm * 32 + mt * 16 + lrow, ks * 2 + lhi) * 4]));
#pragma unroll
        for (int ks = 0; ks < 2; ++ks)
#pragma unroll
            for (int p2 = 0; p2 < 4; ++p2) {
                uint32_t bf[4];
                ldsm4t(bf, smaddr(&Bsm[cur][buB(ks * 16 + lrow, wn * 8 + p2 * 2 + lhi) * 4]));
#pragma unroll
                for (int mt = 0; mt < 2; ++mt) {
                    mma_bf16(acc[mt][p2 * 2 + 0], af[mt][ks], bf[0], bf[1]);
                    mma_bf16(acc[mt][p2 * 2 + 1], af[mt][ks], bf[2], bf[3]);
                }
            }
        if (c + 2 < NC) {
            int cn = c + 2;
            const __nv_bfloat16* Ab; int lda;
            if (cn < splitc) { Ab = A0 + (size_t)cn * 32; lda = lda0; }
            else             { Ab = A1 + (size_t)(cn - splitc) * 32; lda = lda1; }
            stage_async(Asm[cn % 3], Bsm[cn % 3], Ab, lda,
                        Bw + (size_t)(cn * 32) * ldb + n0, ldb, tid);
            CP_COMMIT();
        }
    }
}

#define MMA_EPI_IDS                                       \
    int tid = threadIdx.x;                                \
    int lane = tid & 31, g = lane >> 2, tig = lane & 3;   \
    int wid = tid >> 5, wm = wid & 3, wn = wid >> 2;      \
    (void)lane;

// ---------------- kernel 0: f32 -> bf16 conversions ----------------
__global__ __launch_bounds__(256) void k_cvt(const float* __restrict__ s,
                                             __nv_bfloat16* __restrict__ d, int n4) {
    int i = blockIdx.x * 256 + threadIdx.x;
    int stride = gridDim.x * 256;
    for (; i < n4; i += stride) {
        float4 v = ((const float4*)s)[i];
        ((uint2*)d)[i] = make_uint2(bf16x2(v.x, v.y), bf16x2(v.z, v.w));
    }
}

// ---------------- kernel 1: qk / v projection (+ K^T write) ----------------
__global__ __launch_bounds__(256) void k_proj_mma(
    const float* __restrict__ bqk, const float* __restrict__ bv)
{
    __shared__ __align__(16) uint32_t As[3][2048];
    __shared__ __align__(16) uint32_t Bs[3][2048];
    int m0  = blockIdx.y * 128;
    int n0g = blockIdx.x * 128;
    bool isv = (n0g >= 256);
    const __nv_bfloat16* Bw = isv ? c_wv : c_wqk;
    const float* bias = isv ? bv : bqk;
    int n0 = n0g & 255;
    const __nv_bfloat16* A0 = c_x + (size_t)m0 * DMODEL;
    float acc[2][8][4] = {};
    gemm_bf16(As, Bs, A0, DMODEL, A0, DMODEL, 1 << 20, Bw, DMODEL, n0, 8, acc);

    MMA_EPI_IDS;
    int t = (m0 >= ROWS_HALF);
    int base = m0 - t * ROWS_HALF;
    int bb = base >> 11;
    float* dst = isv ? g_v : g_qk;
    size_t hb = (((size_t)t * NB + bb) * HEADS) * (size_t)SEQN * HD;
#pragma unroll
    for (int mt = 0; mt < 2; ++mt) {
        int r   = m0 + wm * 32 + mt * 16 + g;
        int nn0 = (r - t * ROWS_HALF) & 2047;
#pragma unroll
        for (int nt = 0; nt < 8; ++nt) {
            int c = n0 + wn * 64 + nt * 8 + 2 * tig;
            int h = c >> 6, hd = c & 63;
            float b0v = bias[c], b1v = bias[c + 1];
            float va = acc[mt][nt][0] + b0v, vb = acc[mt][nt][1] + b1v;
            float vc = acc[mt][nt][2] + b0v, vd = acc[mt][nt][3] + b1v;
            size_t d0 = hb + ((size_t)h * SEQN + nn0) * HD + hd;
            size_t d1 = hb + ((size_t)h * SEQN + nn0 + 8) * HD + hd;
            *(float2*)&dst[d0] = make_float2(va, vb);
            *(float2*)&dst[d1] = make_float2(vc, vd);
            if (!isv) {
                size_t tb = ((((size_t)t * NB + bb) * HEADS + h) * HD + hd) * (size_t)SEQN;
                g_qkT[tb + nn0]            = va;
                g_qkT[tb + SEQN + nn0]     = vb;
                g_qkT[tb + nn0 + 8]        = vc;
                g_qkT[tb + SEQN + nn0 + 8] = vd;
            }
        }
    }
}

// ---------------- kernel 3: mo = m @ Wout + bout (bf16 out) ----------------
__global__ __launch_bounds__(256) void k_outproj_mma(const float* __restrict__ bout)
{
    __shared__ __align__(16) uint32_t As[3][2048];
    __shared__ __align__(16) uint32_t Bs[3][2048];
    int m0 = blockIdx.y * 128;
    int n0 = blockIdx.x * 128;
    const __nv_bfloat16* A0 = g_mb + (size_t)m0 * DMODEL;
    float acc[2][8][4] = {};
    gemm_bf16(As, Bs, A0, DMODEL, A0, DMODEL, 1 << 20, c_wot, DMODEL, n0, 8, acc);

    MMA_EPI_IDS;
    uint32_t* mo = (uint32_t*)g_mob;
#pragma unroll
    for (int mt = 0; mt < 2; ++mt) {
        int r = m0 + wm * 32 + mt * 16 + g;
#pragma unroll
        for (int nt = 0; nt < 8; ++nt) {
            int c = n0 + wn * 64 + nt * 8 + 2 * tig;
            float b0v = bout[c], b1v = bout[c + 1];
            mo[((size_t)r * DMODEL + c) >> 1] =
                bf16x2(acc[mt][nt][0] + b0v, acc[mt][nt][1] + b1v);
            mo[((size_t)(r + 8) * DMODEL + c) >> 1] =
                bf16x2(acc[mt][nt][2] + b0v, acc[mt][nt][3] + b1v);
        }
    }
}

// ---------------- kernel 4: y = [x | mo] @ W0 + b0 (f32 out for LN) --------
__global__ __launch_bounds__(256) void k_ffn0_mma(const float* __restrict__ b0)
{
    __shared__ __align__(16) uint32_t As[3][2048];
    __shared__ __align__(16) uint32_t Bs[3][2048];
    int m0 = blockIdx.y * 128;
    int n0 = blockIdx.x * 128;
    const __nv_bfloat16* ax = c_x + (size_t)m0 * DMODEL;
    const __nv_bfloat16* am = g_mob + (size_t)m0 * DMODEL;
    float acc[2][8][4] = {};
    gemm_bf16(As, Bs, ax, DMODEL, am, DMODEL, 8, c_w0, 512, n0, 16, acc);

    MMA_EPI_IDS;
#pragma unroll
    for (int mt = 0; mt < 2; ++mt) {
        int r = m0 + wm * 32 + mt * 16 + g;
#pragma unroll
        for (int nt = 0; nt < 8; ++nt) {
            int c = n0 + wn * 64 + nt * 8 + 2 * tig;
            float b0v = b0[c], b1v = b0[c + 1];
            *(float2*)&g_y[(size_t)r * 512 + c] =
                make_float2(acc[mt][nt][0] + b0v, acc[mt][nt][1] + b1v);
            *(float2*)&g_y[(size_t)(r + 8) * 512 + c] =
                make_float2(acc[mt][nt][2] + b0v, acc[mt][nt][3] + b1v);
        }
    }
}

// ---------------- kernel 6: out = x + y2 @ W3 + b3 ----------------
__global__ __launch_bounds__(256) void k_ffn3_mma(
    const float* __restrict__ x0, const float* __restrict__ x1,
    const float* __restrict__ b3, float* __restrict__ out)
{
    __shared__ __align__(16) uint32_t As[3][2048];
    __shared__ __align__(16) uint32_t Bs[3][2048];
    int m0 = blockIdx.y * 128;
    int n0 = blockIdx.x * 128;
    const __nv_bfloat16* A0 = g_y2 + (size_t)m0 * 512;
    float acc[2][8][4] = {};
    gemm_bf16(As, Bs, A0, 512, A0, 512, 1 << 20, c_w3, DMODEL, n0, 16, acc);

    MMA_EPI_IDS;
    const float* xb = (m0 < ROWS_HALF) ? (x0 + (size_t)m0 * DMODEL)
                                       : (x1 + (size_t)(m0 - ROWS_HALF) * DMODEL);
#pragma unroll
    for (int mt = 0; mt < 2; ++mt) {
        int r  = m0 + wm * 32 + mt * 16 + g;
        int rl = wm * 32 + mt * 16 + g;
#pragma unroll
        for (int nt = 0; nt < 8; ++nt) {
            int c = n0 + wn * 64 + nt * 8 + 2 * tig;
            float b0v = b3[c], b1v = b3[c + 1];
            float2 xv0 = *(const float2*)(xb + (size_t)rl * DMODEL + c);
            float2 xv1 = *(const float2*)(xb + (size_t)(rl + 8) * DMODEL + c);
            *(float2*)&out[(size_t)r * DMODEL + c] =
                make_float2(acc[mt][nt][0] + b0v + xv0.x, acc[mt][nt][1] + b1v + xv0.y);
            *(float2*)&out[(size_t)(r + 8) * DMODEL + c] =
                make_float2(acc[mt][nt][2] + b0v + xv1.x, acc[mt][nt][3] + b1v + xv1.y);
        }
    }
}

// ---------------- kernel 2: tf32 mma flash attention (R12 verbatim; bf16 out) --
#define ATTN_SMEM_WORDS 25088
#define ATTN_SMEM_BYTES (ATTN_SMEM_WORDS * 4)

__global__ __launch_bounds__(256) void k_attn_mma() {
    extern __shared__ uint32_t sm[];
    uint32_t (*Qf)[512][4] = (uint32_t(*)[512][4])(sm);
    uint32_t (*Kf)[256][4] = (uint32_t(*)[256][4])(sm + 8192);
    uint32_t (*Vf)[256][4] = (uint32_t(*)[256][4])(sm + 12288);
    uint32_t (*Pf)[512][4] = (uint32_t(*)[512][4])(sm + 16384);
    float* smax = (float*)(sm + 24576);
    float* ssum = (float*)(sm + 24832);

    int qt = blockIdx.x, bh = blockIdx.y, dir = blockIdx.z;
    int b = bh >> 2, h = bh & 3, kvd = 1 - dir;

    const float* Qb = g_qk  + (((size_t)dir * NB + b) * HEADS + h) * (size_t)SEQN * HD
                            + (size_t)qt * 128 * HD;
    const float* KT = g_qkT + (((size_t)kvd * NB + b) * HEADS + h) * (size_t)HD * SEQN;
    const float* Vb = g_v   + (((size_t)kvd * NB + b) * HEADS + h) * (size_t)SEQN * HD;

    int tid = threadIdx.x, lane = tid & 31, g = lane >> 2, tig = tid & 3;
    int wid = tid >> 5, wm = wid & 3, wn = wid >> 2;

    {
        int ar = tid >> 1, acl = tid & 1;
        int amt = ar >> 4, amr = ar & 15, ag = amr & 7, ahi = amr >> 3;
        uint32_t abase = (uint32_t)((amt * 2 + acl) * 32 + ag * 4);
#pragma unroll
        for (int c = 0; c < 4; ++c) {
            const float* pa = Qb + (size_t)ar * HD + c * 16 + acl * 8;
            float4 r0 = *(const float4*)pa;
            float4 r1 = *(const float4*)(pa + 4);
            float av[8] = {r0.x, r0.y, r0.z, r0.w, r1.x, r1.y, r1.z, r1.w};
#pragma unroll
            for (int i = 0; i < 8; ++i)
                Qf[c][swz(abase + (i & 3))][(i >> 2) * 2 + ahi] = f2tf32(av[i] * 0.125f);
        }
    }

    float Oacc[2][4][4] = {};
    float rmax[2][2] = {{-1e30f, -1e30f}, {-1e30f, -1e30f}};
    float rsum[2][2] = {{0.f, 0.f}, {0.f, 0.f}};

    int pch = tid >> 7, pt = tid & 127;
    int br = pt & 15, nb = pt >> 4;
    int bkk = br & 7, btig = bkk & 3, bjw = (br >> 3) * 2 + (bkk >> 2);

    for (int kt = 0; kt < 32; ++kt) {
        __syncthreads();
#pragma unroll
        for (int pp = 0; pp < 2; ++pp) {
            int ch = pp * 2 + pch;
            const float* ps = KT + (size_t)(ch * 16 + br) * SEQN + kt * 64 + nb * 8;
            float4 r0 = *(const float4*)ps;
            float4 r1 = *(const float4*)(ps + 4);
            float bv[8] = {r0.x, r0.y, r0.z, r0.w, r1.x, r1.y, r1.z, r1.w};
#pragma unroll
            for (int i = 0; i < 8; ++i)
                Kf[ch][swz((uint32_t)(nb * 32 + i * 4 + btig))][bjw] = f2tf32(bv[i]);
            const float* pv = Vb + (size_t)(kt * 64 + ch * 16 + br) * HD + nb * 8;
            float4 v0 = *(const float4*)pv;
            float4 v1 = *(const float4*)(pv + 4);
            float vv[8] = {v0.x, v0.y, v0.z, v0.w, v1.x, v1.y, v1.z, v1.w};
#pragma unroll
            for (int i = 0; i < 8; ++i)
                Vf[ch][swz((uint32_t)(nb * 32 + i * 4 + btig))][bjw] = f2tf32(vv[i]);
        }
        __syncthreads();

        float S[2][4][4] = {};
#pragma unroll
        for (int c = 0; c < 4; ++c) {
            uint32_t af[2][2][4];
#pragma unroll
            for (int mt = 0; mt < 2; ++mt) {
                uint32_t gb = (uint32_t)(((wm * 2 + mt) * 2) * 32 + lane);
                uint4 f0 = *(const uint4*)Qf[c][swz(gb)];
                uint4 f1 = *(const uint4*)Qf[c][swz(gb + 32)];
                af[mt][0][0] = f0.x; af[mt][0][1] = f0.y; af[mt][0][2] = f0.z; af[mt][0][3] = f0.w;
                af[mt][1][0] = f1.x; af[mt][1][1] = f1.y; af[mt][1][2] = f1.z; af[mt][1][3] = f1.w;
            }
#pragma unroll
            for (int nt = 0; nt < 4; ++nt) {
                uint4 fb = *(const uint4*)Kf[c][swz((uint32_t)((wn * 4 + nt) * 32 + lane))];
#pragma unroll
                for (int mt = 0; mt < 2; ++mt) {
                    mma_tf32(S[mt][nt], af[mt][0], fb.x, fb.y);
                    mma_tf32(S[mt][nt], af[mt][1], fb.z, fb.w);
                }
            }
        }

        float tmax[2][2], nm[2][2], corr[2][2], tsum[2][2];
#pragma unroll
        for (int mt = 0; mt < 2; ++mt)
#pragma unroll
            for (int hi = 0; hi < 2; ++hi) {
                float v = fmaxf(S[mt][0][hi * 2], S[mt][0][hi * 2 + 1]);
#pragma unroll
                for (int nt = 1; nt < 4; ++nt)
                    v = fmaxf(v, fmaxf(S[mt][nt][hi * 2], S[mt][nt][hi * 2 + 1]));
                v = fmaxf(v, __shfl_xor_sync(0xffffffffu, v, 1));
                v = fmaxf(v, __shfl_xor_sync(0xffffffffu, v, 2));
                tmax[mt][hi] = v;
            }
        if (tig == 0) {
#pragma unroll
            for (int mt = 0; mt < 2; ++mt)
#pragma unroll
                for (int hi = 0; hi < 2; ++hi)
                    smax[wn * 128 + wm * 32 + mt * 16 + hi * 8 + g] = tmax[mt][hi];
        }
        __syncthreads();
#pragma unroll
        for (int mt = 0; mt < 2; ++mt)
#pragma unroll
            for (int hi = 0; hi < 2; ++hi) {
                int r = wm * 32 + mt * 16 + hi * 8 + g;
                float tm = fmaxf(tmax[mt][hi], smax[(wn ^ 1) * 128 + r]);
                float n2 = fmaxf(rmax[mt][hi], tm);
                nm[mt][hi] = n2;
                corr[mt][hi] = __expf(rmax[mt][hi] - n2);
                rmax[mt][hi] = n2;
                tsum[mt][hi] = 0.f;
            }
#pragma unroll
        for (int mt = 0; mt < 2; ++mt)
#pragma unroll
            for (int nt = 0; nt < 4; ++nt)
#pragma unroll
                for (int hi = 0; hi < 2; ++hi)
#pragma unroll
                    for (int e = 0; e < 2; ++e) {
                        float p = __expf(S[mt][nt][hi * 2 + e] - nm[mt][hi]);
                        tsum[mt][hi] += p;
                        int col = wn * 32 + nt * 8 + 2 * tig + e;
                        int kp = col & 15;
                        uint32_t grp = (uint32_t)(((wm * 2 + mt) * 2 + (kp >> 3)) * 32
                                                  + g * 4 + (kp & 3));
                        Pf[col >> 4][swz(grp)][((kp >> 2) & 1) * 2 + hi] = f2tf32(p);
                    }
#pragma unroll
        for (int mt = 0; mt < 2; ++mt)
#pragma unroll
            for (int hi = 0; hi < 2; ++hi) {
                float v = tsum[mt][hi];
                v += __shfl_xor_sync(0xffffffffu, v, 1);
                v += __shfl_xor_sync(0xffffffffu, v, 2);
                tsum[mt][hi] = v;
#pragma unroll
                for (int nt = 0; nt < 4; ++nt) {
                    Oacc[mt][nt][hi * 2 + 0] *= corr[mt][hi];
                    Oacc[mt][nt][hi * 2 + 1] *= corr[mt][hi];
                }
            }
        if (tig == 0) {
#pragma unroll
            for (int mt = 0; mt < 2; ++mt)
#pragma unroll
                for (int hi = 0; hi < 2; ++hi)
                    ssum[wn * 128 + wm * 32 + mt * 16 + hi * 8 + g] = tsum[mt][hi];
        }
        __syncthreads();
#pragma unroll
        for (int mt = 0; mt < 2; ++mt)
#pragma unroll
            for (int hi = 0; hi < 2; ++hi) {
                int r = wm * 32 + mt * 16 + hi * 8 + g;
                rsum[mt][hi] = rsum[mt][hi] * corr[mt][hi]
                             + tsum[mt][hi] + ssum[(wn ^ 1) * 128 + r];
            }

#pragma unroll
        for (int c = 0; c < 4; ++c) {
            uint32_t af[2][2][4];
#pragma unroll
            for (int mt = 0; mt < 2; ++mt) {
                uint32_t gb = (uint32_t)(((wm * 2 + mt) * 2) * 32 + lane);
                uint4 f0 = *(const uint4*)Pf[c][swz(gb)];
                uint4 f1 = *(const uint4*)Pf[c][swz(gb + 32)];
                af[mt][0][0] = f0.x; af[mt][0][1] = f0.y; af[mt][0][2] = f0.z; af[mt][0][3] = f0.w;
                af[mt][1][0] = f1.x; af[mt][1][1] = f1.y; af[mt][1][2] = f1.z; af[mt][1][3] = f1.w;
            }
#pragma unroll
            for (int nt = 0; nt < 4; ++nt) {
                uint4 fb = *(const uint4*)Vf[c][swz((uint32_t)((wn * 4 + nt) * 32 + lane))];
#pragma unroll
                for (int mt = 0; mt < 2; ++mt) {
                    mma_tf32(Oacc[mt][nt], af[mt][0], fb.x, fb.y);
                    mma_tf32(Oacc[mt][nt], af[mt][1], fb.z, fb.w);
                }
            }
        }
    }

    // epilogue: normalize, write bf16 g_mb (cvt.rn of the same floats as before)
    size_t rowbase = (size_t)dir * ROWS_HALF + (size_t)b * SEQN + (size_t)qt * 128;
    uint32_t* mb = (uint32_t*)g_mb;
#pragma unroll
    for (int mt = 0; mt < 2; ++mt)
#pragma unroll
        for (int hi = 0; hi < 2; ++hi) {
            float inv = 1.0f / rsum[mt][hi];
            size_t row = rowbase + wm * 32 + mt * 16 + hi * 8 + g;
#pragma unroll
            for (int nt = 0; nt < 4; ++nt) {
                int col = wn * 32 + nt * 8 + 2 * tig;
                mb[(row * DMODEL + h * HD + col) >> 1] =
                    bf16x2(Oacc[mt][nt][hi * 2 + 0] * inv,
                           Oacc[mt][nt][hi * 2 + 1] * inv);
            }
        }
}

// ---------------- kernel 5: layernorm + exact gelu (f32 in, bf16 out) -------
__global__ __launch_bounds__(128) void k_lngelu(const float* __restrict__ lns,
                                                const float* __restrict__ lnb) {
    __shared__ float red[4];
    int row = blockIdx.x;
    int t = threadIdx.x;
    const float* yp = g_y + (size_t)row * 512 + t * 4;
    float4 v = *(const float4*)yp;

    float s = v.x + v.y + v.z + v.w;
#pragma unroll
    for (int off = 16; off; off >>= 1) s += __shfl_xor_sync(0xffffffffu, s, off);
    if ((t & 31) == 0) red[t >> 5] = s;
    __syncthreads();
    float mean = (red[0] + red[1] + red[2] + red[3]) * (1.0f / 512.0f);

    float d0 = v.x - mean, d1 = v.y - mean, d2 = v.z - mean, d3 = v.w - mean;
    float ss = d0 * d0 + d1 * d1 + d2 * d2 + d3 * d3;
#pragma unroll
    for (int off = 16; off; off >>= 1) ss += __shfl_xor_sync(0xffffffffu, ss, off);
    __syncthreads();
    if ((t & 31) == 0) red[t >> 5] = ss;
    __syncthreads();
    float var = (red[0] + red[1] + red[2] + red[3]) * (1.0f / 512.0f);
    float rstd = rsqrtf(var + 1e-5f);

    int c = t * 4;
    float g0 = d0 * rstd * lns[c + 0] + lnb[c + 0];
    float g1 = d1 * rstd * lns[c + 1] + lnb[c + 1];
    float g2 = d2 * rstd * lns[c + 2] + lnb[c + 2];
    float g3 = d3 * rstd * lns[c + 3] + lnb[c + 3];
    const float is2 = 0.70710678118654752f;
    g0 = 0.5f * g0 * (1.0f + erff(g0 * is2));
    g1 = 0.5f * g1 * (1.0f + erff(g1 * is2));
    g2 = 0.5f * g2 * (1.0f + erff(g2 * is2));
    g3 = 0.5f * g3 * (1.0f + erff(g3 * is2));
    ((uint2*)g_y2)[((size_t)row * 512 + c) >> 2] =
        make_uint2(bf16x2(g0, g1), bf16x2(g2, g3));
}

// ---------------- launch ----------------
extern "C" void kernel_launch(void* const* d_in, const int* in_sizes, int n_in,
                              void* d_out, int out_size) {
    const float* x0   = (const float*)d_in[0];
    const float* x1   = (const float*)d_in[1];
    const float* Wqk  = (const float*)d_in[2];
    const float* bqk  = (const float*)d_in[3];
    const float* Wv   = (const float*)d_in[4];
    const float* bv   = (const float*)d_in[5];
    const float* Wout = (const float*)d_in[6];
    const float* bout = (const float*)d_in[7];
    const float* W0   = (const float*)d_in[8];
    const float* b0   = (const float*)d_in[9];
    const float* lns  = (const float*)d_in[10];
    const float* lnb  = (const float*)d_in[11];
    const float* W3   = (const float*)d_in[12];
    const float* b3   = (const float*)d_in[13];
    float* out = (float*)d_out;

    cudaFuncSetAttribute(k_attn_mma, cudaFuncAttributeMaxDynamicSharedMemorySize,
                         ATTN_SMEM_BYTES);

    __nv_bfloat16 *dcx, *dwqk, *dwv, *dwot, *dw0, *dw3;
    cudaGetSymbolAddress((void**)&dcx,  c_x);
    cudaGetSymbolAddress((void**)&dwqk, c_wqk);
    cudaGetSymbolAddress((void**)&dwv,  c_wv);
    cudaGetSymbolAddress((void**)&dwot, c_wot);
    cudaGetSymbolAddress((void**)&dw0,  c_w0);
    cudaGetSymbolAddress((void**)&dw3,  c_w3);

    k_cvt<<<512, 256>>>(x0, dcx, ROWS_HALF * DMODEL / 4);
    k_cvt<<<512, 256>>>(x1, dcx + (size_t)ROWS_HALF * DMODEL, ROWS_HALF * DMODEL / 4);
    k_cvt<<<64, 256>>>(Wqk, dwqk, DMODEL * DMODEL / 4);
    k_cvt<<<64, 256>>>(Wv, dwv, DMODEL * DMODEL / 4);
    k_cvt<<<64, 256>>>(Wout, dwot, DMODEL * DMODEL / 4);
    k_cvt<<<128, 256>>>(W0, dw0, 512 * 512 / 4);
    k_cvt<<<64, 256>>>(W3, dw3, 512 * DMODEL / 4);

    k_proj_mma   <<<dim3(4, 128), 256>>>(bqk, bv);
    k_attn_mma   <<<dim3(16, 16, 2), 256, ATTN_SMEM_BYTES>>>();
    k_outproj_mma<<<dim3(2, 128), 256>>>(bout);
    k_ffn0_mma   <<<dim3(4, 128), 256>>>(b0);
    k_lngelu     <<<ROWS_TOT, 128>>>(lns, lnb);
    k_ffn3_mma   <<<dim3(2, 128), 256>>>(x0, x1, b3, out);
}